// round 15
// baseline (speedup 1.0000x reference)
#include <cuda_runtime.h>
#include <cuda_fp16.h>
#include <cstdint>
#include <cstdio>

// Problem constants
namespace {
constexpr int Bb = 4, Tt = 4096, Cc = 2048, Hh = 16, DhD = 128;
constexpr int Mrows = Bb * Tt;            // 16384
constexpr int NCHUNK = 64;                // scan chunks
constexpr int LCH = Tt / NCHUNK;          // 64 steps per chunk
// GEMM pipeline: 4 stages, prefetch distance 3. One stage row = 16 b32 words
// = 32 fp16 halves of K. 64 mainloop iterations cover K=2048.
constexpr int GST = 4;
constexpr int STAGE_W = 128 * 16;         // 2048 words per (matrix,stage)
constexpr int GEMM_SMEM = 2 * GST * STAGE_W * 4 + 128 * 4 * 4;  // 67584 B
}

// ---------------- scratch (static device globals; no allocation allowed) ---
__device__ __half g_xconv[(size_t)Bb * Tt * Cc];
__device__ __half g_q   [(size_t)Bb * Tt * Cc];
__device__ __half g_k   [(size_t)Bb * Tt * Cc];
__device__ __half g_v   [(size_t)Bb * Tt * Cc];
__device__ __half g_gate[(size_t)Bb * Tt * Cc];
__device__ __half g_att [(size_t)Bb * Tt * Cc];
__device__ __half g_y   [(size_t)Bb * Tt * Cc];      // fp16 pre-LN output
__device__ __half g_xt  [(size_t)Bb * Tt * Cc];      // fp16-rounded x
__device__ __half g_Wqt [(size_t)Cc * Cc];
__device__ __half g_Wkt [(size_t)Cc * Cc];
__device__ __half g_Wvt [(size_t)Cc * Cc];
__device__ __half g_Wot [(size_t)Cc * Cc];
__device__ __half g_Wgt [(size_t)Cc * Cc];
__device__ float  g_F    [(size_t)Bb * Hh * NCHUNK * DhD];
__device__ float  g_carry[(size_t)Bb * Hh * NCHUNK * DhD];

// ---------------- helpers --------------------------------------------------
__device__ __forceinline__ uint32_t pack_h2(float a, float b) {
    __half2 h = __floats2half2_rn(a, b);
    return *reinterpret_cast<uint32_t*>(&h);
}
__device__ __forceinline__ float2 unpack_h2(uint32_t u) {
    return __half22float2(*reinterpret_cast<__half2*>(&u));
}

__device__ __forceinline__ void mma_f16(float& d0, float& d1, float& d2, float& d3,
                                        uint32_t a0, uint32_t a1, uint32_t a2, uint32_t a3,
                                        uint32_t b0, uint32_t b1) {
    asm volatile(
        "mma.sync.aligned.m16n8k16.row.col.f32.f16.f16.f32 "
        "{%0,%1,%2,%3}, {%4,%5,%6,%7}, {%8,%9}, {%0,%1,%2,%3};\n"
        : "+f"(d0), "+f"(d1), "+f"(d2), "+f"(d3)
        : "r"(a0), "r"(a1), "r"(a2), "r"(a3), "r"(b0), "r"(b1));
}

#define LDMATRIX_X4(r0, r1, r2, r3, addr) \
    asm volatile("ldmatrix.sync.aligned.m8n8.x4.shared.b16 {%0,%1,%2,%3}, [%4];" \
                 : "=r"(r0), "=r"(r1), "=r"(r2), "=r"(r3) : "r"(addr))

// ---------------- 0) fp16 conversion of the 5 weight matrices (one launch) --
__global__ void cvt5_f16_kernel(const float* __restrict__ w0, __half* __restrict__ o0,
                                const float* __restrict__ w1, __half* __restrict__ o1,
                                const float* __restrict__ w2, __half* __restrict__ o2,
                                const float* __restrict__ w3, __half* __restrict__ o3,
                                const float* __restrict__ w4, __half* __restrict__ o4) {
    const int seg = blockIdx.x >> 11;                 // 2048 blocks per weight
    const int i   = (blockIdx.x & 2047) * 256 + threadIdx.x;  // 8-elem group idx
    const float* in;
    __half* out;
    switch (seg) {
        case 0: in = w0; out = o0; break;
        case 1: in = w1; out = o1; break;
        case 2: in = w2; out = o2; break;
        case 3: in = w3; out = o3; break;
        default: in = w4; out = o4; break;
    }
    float4 v0 = reinterpret_cast<const float4*>(in)[i * 2];
    float4 v1 = reinterpret_cast<const float4*>(in)[i * 2 + 1];
    uint4 pk;
    pk.x = pack_h2(v0.x, v0.y);
    pk.y = pack_h2(v0.z, v0.w);
    pk.z = pack_h2(v1.x, v1.y);
    pk.w = pack_h2(v1.z, v1.w);
    reinterpret_cast<uint4*>(out)[i] = pk;
}

// ---------------- 1) causal depthwise conv (K=4) + SiLU + x fp16 side-out ---
__global__ void conv_silu_kernel(const float* __restrict__ x,
                                 const float* __restrict__ w,
                                 const float* __restrict__ bias) {
    int vid = blockIdx.x * blockDim.x + threadIdx.x;    // over B*T*C/4
    int cq  = vid & (Cc / 4 - 1);                       // channel quad
    int bt  = vid >> 9;                                 // /(2048/4)
    int t   = bt & (Tt - 1);
    int c   = cq * 4;

    const float4* x4 = reinterpret_cast<const float4*>(x);
    int base = (bt - t) * (Cc / 4) + cq;                // b*T*C/4 + cq

    float4 wr0 = reinterpret_cast<const float4*>(w)[c + 0];
    float4 wr1 = reinterpret_cast<const float4*>(w)[c + 1];
    float4 wr2 = reinterpret_cast<const float4*>(w)[c + 2];
    float4 wr3 = reinterpret_cast<const float4*>(w)[c + 3];
    float4 bb  = reinterpret_cast<const float4*>(bias)[cq];

    float4 a = bb;
    float4 xt3;
    #pragma unroll
    for (int j = 0; j < 4; j++) {
        int tt = t - 3 + j;
        if (tt >= 0) {
            float4 xv = x4[base + tt * (Cc / 4)];
            if (j == 3) xt3 = xv;
            float wj0 = (&wr0.x)[j], wj1 = (&wr1.x)[j], wj2 = (&wr2.x)[j], wj3 = (&wr3.x)[j];
            a.x = fmaf(xv.x, wj0, a.x);
            a.y = fmaf(xv.y, wj1, a.y);
            a.z = fmaf(xv.z, wj2, a.z);
            a.w = fmaf(xv.w, wj3, a.w);
        }
    }

    uint2 sc;
    sc.x = pack_h2(a.x / (1.0f + expf(-a.x)), a.y / (1.0f + expf(-a.y)));
    sc.y = pack_h2(a.z / (1.0f + expf(-a.z)), a.w / (1.0f + expf(-a.w)));
    reinterpret_cast<uint2*>(g_xconv)[vid] = sc;

    uint2 xr;
    xr.x = pack_h2(xt3.x, xt3.y);
    xr.y = pack_h2(xt3.z, xt3.w);
    reinterpret_cast<uint2*>(g_xt)[vid] = xr;
}

// ---------------- 2) FP16 GEMM tile body (4-stage pipeline, ldmatrix) -------
// Computes one 128x128 tile of Out = A[M,2048] * W[128-col slab]^T, fp16 in,
// fp32 accumulate. OutT = __half (qkvg, y) or float.
// mode 0: plain.  mode 1: sigmoid(out + bias[col]).  mode 2: per-row l2norm.
// smem layout per (matrix,stage): 128 rows x 16 words, XOR-swizzled chunks:
//   word(row,w) at row*16 + (((w>>2) ^ ((row>>1)&3))<<2) + (w&3)
template <typename OutT>
__device__ __forceinline__
void gemm_tile_body(const __half* __restrict__ A, const __half* __restrict__ W,
                    OutT* __restrict__ Out, const float* __restrict__ bias,
                    int mode, int bm, int bn) {
    constexpr int BM = 128;
    constexpr int KH = 32;                // K halves per stage
    constexpr int KCH = Cc / KH;          // 64 iterations
    constexpr int N = Cc;

    extern __shared__ uint32_t dyn[];
    float* red = (float*)(dyn + 2 * GST * STAGE_W);  // 128*4 floats

    const int tid  = threadIdx.x;
    const int warp = tid >> 5, lane = tid & 31;
    const int gid  = lane >> 2, tg = lane & 3;
    const int wm   = warp & 1;       // 0..1  -> 64-row slab
    const int wn   = warp >> 1;      // 0..3  -> 32-col slab

    const int lr = tid >> 2;         // 0..63  (loader row)
    const int lc = tid & 3;          // chunk 0..3 (8 halves each)

    uint32_t sA = (uint32_t)__cvta_generic_to_shared(dyn);
    uint32_t sB = sA + (uint32_t)(GST * STAGE_W) * 4u;

    // ---- per-lane ldmatrix byte offsets within a stage (loop-invariant) ----
    const int lq  = lane >> 3;       // matrix quad 0..3
    const int lr8 = lane & 7;
    uint32_t aoff[2][4];             // [half][mt]
    uint32_t boff[2][2];             // [half][ntp]
    #pragma unroll
    for (int half = 0; half < 2; half++) {
        #pragma unroll
        for (int mt = 0; mt < 4; mt++) {
            int row   = wm * 64 + mt * 16 + (lq & 1) * 8 + lr8;
            int sw    = (row >> 1) & 3;
            int chunk = half * 2 + (lq >> 1);
            aoff[half][mt] = (uint32_t)(row * 64 + ((chunk ^ sw) << 4));
        }
        #pragma unroll
        for (int ntp = 0; ntp < 2; ntp++) {
            int col   = wn * 32 + (2 * ntp + (lq >> 1)) * 8 + lr8;
            int sw    = (col >> 1) & 3;
            int chunk = half * 2 + (lq & 1);
            boff[half][ntp] = (uint32_t)(col * 64 + ((chunk ^ sw) << 4));
        }
    }

    auto issue = [&](int s, int k0) {   // k0 in halves
        #pragma unroll
        for (int r = 0; r < 2; r++) {
            int row = lr + r * 64;
            int sw  = (row >> 1) & 3;
            uint32_t off = (uint32_t)(s * BM * 16 + row * 16 + ((lc ^ sw) << 2)) * 4u;
            const __half* gA = A + (size_t)(bm + row) * Cc + k0 + lc * 8;
            asm volatile("cp.async.cg.shared.global [%0], [%1], 16;\n"
                         :: "r"(sA + off), "l"(gA));
            const __half* gB = W + (size_t)(bn + row) * Cc + k0 + lc * 8;
            asm volatile("cp.async.cg.shared.global [%0], [%1], 16;\n"
                         :: "r"(sB + off), "l"(gB));
        }
        asm volatile("cp.async.commit_group;\n");
    };

    float acc[4][4][4] = {};

    issue(0, 0);
    issue(1, KH);
    issue(2, 2 * KH);

    int s = 0;
    for (int i = 0; i < KCH; i++) {
        if (i < KCH - 2)       asm volatile("cp.async.wait_group 2;\n" ::: "memory");
        else if (i == KCH - 2) asm volatile("cp.async.wait_group 1;\n" ::: "memory");
        else                   asm volatile("cp.async.wait_group 0;\n" ::: "memory");
        __syncthreads();

        if (i + 3 < KCH) {
            int s2 = s + 3; if (s2 >= GST) s2 -= GST;
            issue(s2, (i + 3) * KH);
        }

        const uint32_t stA = sA + (uint32_t)(s * STAGE_W) * 4u;
        const uint32_t stB = sB + (uint32_t)(s * STAGE_W) * 4u;

        // Fragment loads: 8 A + 4 B ldmatrix.x4 per iteration.
        uint32_t af[2][4][4], bf[2][4][2];
        #pragma unroll
        for (int half = 0; half < 2; half++) {
            #pragma unroll
            for (int mt = 0; mt < 4; mt++)
                LDMATRIX_X4(af[half][mt][0], af[half][mt][1],
                            af[half][mt][2], af[half][mt][3],
                            stA + aoff[half][mt]);
            #pragma unroll
            for (int ntp = 0; ntp < 2; ntp++)
                LDMATRIX_X4(bf[half][2 * ntp][0],     bf[half][2 * ntp][1],
                            bf[half][2 * ntp + 1][0], bf[half][2 * ntp + 1][1],
                            stB + boff[half][ntp]);
        }
        #pragma unroll
        for (int half = 0; half < 2; half++)
            #pragma unroll
            for (int mt = 0; mt < 4; mt++)
                #pragma unroll
                for (int nt = 0; nt < 4; nt++)
                    mma_f16(acc[mt][nt][0], acc[mt][nt][1], acc[mt][nt][2], acc[mt][nt][3],
                            af[half][mt][0], af[half][mt][1], af[half][mt][2], af[half][mt][3],
                            bf[half][nt][0], bf[half][nt][1]);
        s++; if (s >= GST) s = 0;
    }

    // ---- fused l2norm over the 128-col tile (mode 2, tile == one head) -----
    if (mode == 2) {
        __syncthreads();
        float invLo[4], invHi[4];
        #pragma unroll
        for (int mt = 0; mt < 4; mt++) {
            float slo = 0.0f, shi = 0.0f;
            #pragma unroll
            for (int nt = 0; nt < 4; nt++) {
                slo = fmaf(acc[mt][nt][0], acc[mt][nt][0], slo);
                slo = fmaf(acc[mt][nt][1], acc[mt][nt][1], slo);
                shi = fmaf(acc[mt][nt][2], acc[mt][nt][2], shi);
                shi = fmaf(acc[mt][nt][3], acc[mt][nt][3], shi);
            }
            slo += __shfl_xor_sync(0xffffffffu, slo, 1);
            slo += __shfl_xor_sync(0xffffffffu, slo, 2);
            shi += __shfl_xor_sync(0xffffffffu, shi, 1);
            shi += __shfl_xor_sync(0xffffffffu, shi, 2);
            if (tg == 0) {
                int r = wm * 64 + mt * 16 + gid;
                red[r * 4 + wn]       = slo;
                red[(r + 8) * 4 + wn] = shi;
            }
        }
        __syncthreads();
        #pragma unroll
        for (int mt = 0; mt < 4; mt++) {
            int r = wm * 64 + mt * 16 + gid;
            float slo = red[r * 4 + 0] + red[r * 4 + 1] + red[r * 4 + 2] + red[r * 4 + 3];
            float shi = red[(r + 8) * 4 + 0] + red[(r + 8) * 4 + 1]
                      + red[(r + 8) * 4 + 2] + red[(r + 8) * 4 + 3];
            invLo[mt] = 1.0f / fmaxf(sqrtf(slo), 1e-12f);
            invHi[mt] = 1.0f / fmaxf(sqrtf(shi), 1e-12f);
        }
        #pragma unroll
        for (int mt = 0; mt < 4; mt++)
            #pragma unroll
            for (int nt = 0; nt < 4; nt++) {
                acc[mt][nt][0] *= invLo[mt];
                acc[mt][nt][1] *= invLo[mt];
                acc[mt][nt][2] *= invHi[mt];
                acc[mt][nt][3] *= invHi[mt];
            }
    }

    // epilogue stores
    #pragma unroll
    for (int mt = 0; mt < 4; mt++) {
        #pragma unroll
        for (int nt = 0; nt < 4; nt++) {
            int row = bm + wm * 64 + mt * 16 + gid;
            int col = bn + wn * 32 + nt * 8 + tg * 2;
            float v0 = acc[mt][nt][0], v1 = acc[mt][nt][1];
            float v2 = acc[mt][nt][2], v3 = acc[mt][nt][3];
            if (mode == 1) {
                float b0 = bias[col], b1 = bias[col + 1];
                v0 = 1.0f / (1.0f + expf(-(v0 + b0)));
                v1 = 1.0f / (1.0f + expf(-(v1 + b1)));
                v2 = 1.0f / (1.0f + expf(-(v2 + b0)));
                v3 = 1.0f / (1.0f + expf(-(v3 + b1)));
            }
            if constexpr (sizeof(OutT) == 2) {
                *reinterpret_cast<uint32_t*>(
                    (__half*)Out + (size_t)row * N + col)       = pack_h2(v0, v1);
                *reinterpret_cast<uint32_t*>(
                    (__half*)Out + (size_t)(row + 8) * N + col) = pack_h2(v2, v3);
            } else {
                *reinterpret_cast<float2*>(
                    (float*)Out + (size_t)row * N + col)        = make_float2(v0, v1);
                *reinterpret_cast<float2*>(
                    (float*)Out + (size_t)(row + 8) * N + col)  = make_float2(v2, v3);
            }
        }
    }
}

// Combined q/k/v/gate projection: one launch, 64 column-tiles x 128 row-tiles.
// seg = blockIdx.x>>4: 0=q(mode2) 1=k(mode2) 2=v(mode0) 3=gate(mode1, A=xconv)
__global__ __launch_bounds__(256, 2)
void gemm_qkvg_kernel(const float* __restrict__ gate_b) {
    const int seg = blockIdx.x >> 4;
    const int bn  = (blockIdx.x & 15) * 128;
    const int bm  = blockIdx.y * 128;

    const __half* A;
    const __half* W;
    __half* Out;
    int mode;
    switch (seg) {
        case 0:  A = g_xt;    W = g_Wqt; Out = g_q;    mode = 2; break;
        case 1:  A = g_xt;    W = g_Wkt; Out = g_k;    mode = 2; break;
        case 2:  A = g_xt;    W = g_Wvt; Out = g_v;    mode = 0; break;
        default: A = g_xconv; W = g_Wgt; Out = g_gate; mode = 1; break;
    }
    gemm_tile_body<__half>(A, W, Out, gate_b, mode, bm, bn);
}

// Output projection: y = att * Wo^T (mode 0, fp16 out; LN reads half)
__global__ __launch_bounds__(256, 2)
void gemm_out_kernel() {
    gemm_tile_body<__half>(g_att, g_Wot, g_y, nullptr, 0, blockIdx.y * 128, blockIdx.x * 128);
}

// ---------------- 4) chunked decayed scan (fp16 in, fp32 math) -------------
__global__ void scan_pass1(const __half* __restrict__ k, const __half* __restrict__ v,
                           const float* __restrict__ gamma) {
    int wid  = threadIdx.x >> 5, lane = threadIdx.x & 31;
    int blk  = blockIdx.x * 4 + wid;          // 0..4095
    int c    = blk & (NCHUNK - 1);
    int bh   = blk >> 6;
    int h    = bh & (Hh - 1);
    int b    = bh >> 4;
    float g  = gamma[h];
    const uint2* k2 = reinterpret_cast<const uint2*>(k);
    const uint2* v2 = reinterpret_cast<const uint2*>(v);
    size_t idx = ((size_t)(b * Tt + c * LCH) * Cc + h * DhD) / 4 + lane;
    float4 S = make_float4(0.f, 0.f, 0.f, 0.f);
    #pragma unroll 4
    for (int i = 0; i < LCH; i++) {
        uint2 ku = k2[idx], vu = v2[idx];
        float2 k0 = unpack_h2(ku.x), k1 = unpack_h2(ku.y);
        float2 va = unpack_h2(vu.x), vb = unpack_h2(vu.y);
        S.x = fmaf(g, S.x, k0.x * va.x);
        S.y = fmaf(g, S.y, k0.y * va.y);
        S.z = fmaf(g, S.z, k1.x * vb.x);
        S.w = fmaf(g, S.w, k1.y * vb.y);
        idx += Cc / 4;
    }
    reinterpret_cast<float4*>(g_F)[((size_t)bh * NCHUNK + c) * (DhD / 4) + lane] = S;
}

__global__ void scan_pass2(const float* __restrict__ gamma) {
    int tid = blockIdx.x * blockDim.x + threadIdx.x;   // over Bb*Hh*DhD/4 = 2048
    int d4  = tid & (DhD / 4 - 1);
    int bh  = tid >> 5;
    int h   = bh & (Hh - 1);
    float g  = gamma[h];
    float gL = powf(g, (float)LCH);     // exact 1.0 for gamma=1 head
    const float4* F4 = reinterpret_cast<const float4*>(g_F);
    float4* C4       = reinterpret_cast<float4*>(g_carry);
    float4 carry = make_float4(0.f, 0.f, 0.f, 0.f);
    for (int c = 0; c < NCHUNK; c++) {
        size_t o = ((size_t)bh * NCHUNK + c) * (DhD / 4) + d4;
        C4[o] = carry;
        float4 f = F4[o];
        carry.x = fmaf(gL, carry.x, f.x);
        carry.y = fmaf(gL, carry.y, f.y);
        carry.z = fmaf(gL, carry.z, f.z);
        carry.w = fmaf(gL, carry.w, f.w);
    }
}

__global__ void scan_pass3(const __half* __restrict__ k, const __half* __restrict__ v,
                           const __half* __restrict__ q, const __half* __restrict__ gate,
                           const float* __restrict__ gamma) {
    int wid  = threadIdx.x >> 5, lane = threadIdx.x & 31;
    int blk  = blockIdx.x * 4 + wid;
    int c    = blk & (NCHUNK - 1);
    int bh   = blk >> 6;
    int h    = bh & (Hh - 1);
    int b    = bh >> 4;
    float g  = gamma[h];
    const uint2* k2 = reinterpret_cast<const uint2*>(k);
    const uint2* v2 = reinterpret_cast<const uint2*>(v);
    const uint2* q2 = reinterpret_cast<const uint2*>(q);
    const uint2* g2 = reinterpret_cast<const uint2*>(gate);
    uint2* a2       = reinterpret_cast<uint2*>(g_att);   // 4 halves per slot
    float4 S = reinterpret_cast<const float4*>(g_carry)
                   [((size_t)bh * NCHUNK + c) * (DhD / 4) + lane];
    size_t idx = ((size_t)(b * Tt + c * LCH) * Cc + h * DhD) / 4 + lane;
    #pragma unroll 4
    for (int i = 0; i < LCH; i++) {
        uint2 ku = k2[idx], vu = v2[idx];
        float2 k0 = unpack_h2(ku.x), k1 = unpack_h2(ku.y);
        float2 va = unpack_h2(vu.x), vb = unpack_h2(vu.y);
        S.x = fmaf(g, S.x, k0.x * va.x);
        S.y = fmaf(g, S.y, k0.y * va.y);
        S.z = fmaf(g, S.z, k1.x * vb.x);
        S.w = fmaf(g, S.w, k1.y * vb.y);
        uint2 gu = g2[idx], qu = q2[idx];
        float2 g0 = unpack_h2(gu.x), g1 = unpack_h2(gu.y);
        float2 q0 = unpack_h2(qu.x), q1 = unpack_h2(qu.y);
        uint2 o;
        o.x = pack_h2(g0.x * S.x * q0.x, g0.y * S.y * q0.y);
        o.y = pack_h2(g1.x * S.z * q1.x, g1.y * S.w * q1.y);
        a2[idx] = o;
        idx += Cc / 4;
    }
}

// ---------------- 5) LayerNorm over C=2048 (fp16 in, fp32 out) --------------
__global__ __launch_bounds__(256)
void ln_kernel(const __half* __restrict__ y, const float* __restrict__ lw,
               const float* __restrict__ lb, float* __restrict__ out) {
    int row = blockIdx.x;
    int tid = threadIdx.x;
    const uint4* yr = reinterpret_cast<const uint4*>(y + (size_t)row * Cc);
    float4* orow    = reinterpret_cast<float4*>(out + (size_t)row * Cc);

    uint4 u = yr[tid];                       // 8 halves per thread
    float2 p0 = unpack_h2(u.x), p1 = unpack_h2(u.y);
    float2 p2 = unpack_h2(u.z), p3 = unpack_h2(u.w);
    float v[8] = {p0.x, p0.y, p1.x, p1.y, p2.x, p2.y, p3.x, p3.y};

    float sum = 0.0f, sq = 0.0f;
    #pragma unroll
    for (int i = 0; i < 8; i++) { sum += v[i]; sq = fmaf(v[i], v[i], sq); }

    #pragma unroll
    for (int o = 16; o; o >>= 1) {
        sum += __shfl_xor_sync(0xffffffffu, sum, o);
        sq  += __shfl_xor_sync(0xffffffffu, sq, o);
    }
    __shared__ float ssum[8], ssq[8];
    __shared__ float s_mu, s_inv;
    int warp = tid >> 5, lane = tid & 31;
    if (lane == 0) { ssum[warp] = sum; ssq[warp] = sq; }
    __syncthreads();
    if (tid == 0) {
        float ts = 0.0f, tq = 0.0f;
        #pragma unroll
        for (int i = 0; i < 8; i++) { ts += ssum[i]; tq += ssq[i]; }
        float mu  = ts / (float)Cc;
        float var = tq / (float)Cc - mu * mu;
        s_mu  = mu;
        s_inv = rsqrtf(var + 1e-5f);
    }
    __syncthreads();
    float mu = s_mu, inv = s_inv;

    const float4 w0 = reinterpret_cast<const float4*>(lw)[tid * 2];
    const float4 w1 = reinterpret_cast<const float4*>(lw)[tid * 2 + 1];
    const float4 b0 = reinterpret_cast<const float4*>(lb)[tid * 2];
    const float4 b1 = reinterpret_cast<const float4*>(lb)[tid * 2 + 1];

    float4 o0, o1;
    o0.x = (v[0] - mu) * inv * w0.x + b0.x;
    o0.y = (v[1] - mu) * inv * w0.y + b0.y;
    o0.z = (v[2] - mu) * inv * w0.z + b0.z;
    o0.w = (v[3] - mu) * inv * w0.w + b0.w;
    o1.x = (v[4] - mu) * inv * w1.x + b1.x;
    o1.y = (v[5] - mu) * inv * w1.y + b1.y;
    o1.z = (v[6] - mu) * inv * w1.z + b1.z;
    o1.w = (v[7] - mu) * inv * w1.w + b1.w;
    orow[tid * 2]     = o0;
    orow[tid * 2 + 1] = o1;
}

// ---------------- host orchestration ---------------------------------------
extern "C" void kernel_launch(void* const* d_in, const int* in_sizes, int n_in,
                              void* d_out, int out_size) {
    (void)in_sizes; (void)n_in; (void)out_size;
    const float* x      = (const float*)d_in[0];
    const float* Wq     = (const float*)d_in[1];
    const float* Wk     = (const float*)d_in[2];
    const float* Wv     = (const float*)d_in[3];
    const float* Wo     = (const float*)d_in[4];
    const float* conv_w = (const float*)d_in[5];
    const float* conv_b = (const float*)d_in[6];
    const float* gate_w = (const float*)d_in[7];
    const float* gate_b = (const float*)d_in[8];
    const float* ln_w   = (const float*)d_in[9];
    const float* ln_b   = (const float*)d_in[10];
    const float* gamma  = (const float*)d_in[11];

    __half *p_q, *p_k, *p_v, *p_gate, *p_y;
    __half *p_Wqt, *p_Wkt, *p_Wvt, *p_Wot, *p_Wgt;
    cudaGetSymbolAddress((void**)&p_q, g_q);
    cudaGetSymbolAddress((void**)&p_k, g_k);
    cudaGetSymbolAddress((void**)&p_v, g_v);
    cudaGetSymbolAddress((void**)&p_gate, g_gate);
    cudaGetSymbolAddress((void**)&p_y, g_y);
    cudaGetSymbolAddress((void**)&p_Wqt, g_Wqt);
    cudaGetSymbolAddress((void**)&p_Wkt, g_Wkt);
    cudaGetSymbolAddress((void**)&p_Wvt, g_Wvt);
    cudaGetSymbolAddress((void**)&p_Wot, g_Wot);
    cudaGetSymbolAddress((void**)&p_Wgt, g_Wgt);

    // allow 66KB dynamic smem on the GEMM kernels (idempotent)
    cudaFuncSetAttribute(gemm_qkvg_kernel, cudaFuncAttributeMaxDynamicSharedMemorySize, GEMM_SMEM);
    cudaFuncSetAttribute(gemm_out_kernel,  cudaFuncAttributeMaxDynamicSharedMemorySize, GEMM_SMEM);

    // 0) convert the 5 weight matrices to fp16 in one launch
    const int wBlocks = (Cc * Cc) / 2048;  // 2048 blocks per weight
    cvt5_f16_kernel<<<5 * wBlocks, 256>>>(Wq, p_Wqt, Wk, p_Wkt, Wv, p_Wvt,
                                          Wo, p_Wot, gate_w, p_Wgt);

    // 1) depthwise conv + SiLU (float4); also emits fp16 x (g_xt)
    conv_silu_kernel<<<(Mrows * Cc / 4) / 256, 256>>>(x, conv_w, conv_b);

    // 2) all four projections in ONE launch (q, k, v, gate) — fp16 outputs
    dim3 qgrid(64, Mrows / 128);   // 64 col-tiles (4 segs x 16), 128 row-tiles
    gemm_qkvg_kernel<<<qgrid, 256, GEMM_SMEM>>>(gate_b);

    // 3) decayed scan (chunked, exact); fp16 inputs, fp32 recurrence
    scan_pass1<<<Bb * Hh * NCHUNK / 4, 128>>>(p_k, p_v, gamma);
    scan_pass2<<<16, 128>>>(gamma);
    scan_pass3<<<Bb * Hh * NCHUNK / 4, 128>>>(p_k, p_v, p_q, p_gate, gamma);

    // 4) output projection (fp16 y) + LayerNorm (fp32 out)
    dim3 ogrid(Cc / 128, Mrows / 128);   // (16, 128)
    gemm_out_kernel<<<ogrid, 256, GEMM_SMEM>>>();
    ln_kernel<<<Mrows, 256>>>(p_y, ln_w, ln_b, (float*)d_out);
}

// round 16
// speedup vs baseline: 1.0854x; 1.0854x over previous
#include <cuda_runtime.h>
#include <cuda_fp16.h>
#include <cstdint>
#include <cstdio>

// Problem constants
namespace {
constexpr int Bb = 4, Tt = 4096, Cc = 2048, Hh = 16, DhD = 128;
constexpr int Mrows = Bb * Tt;            // 16384
constexpr int NCHUNK = 64;                // scan chunks
constexpr int LCH = Tt / NCHUNK;          // 64 steps per chunk
// GEMM pipeline: 4 stages, prefetch distance 3. One stage row = 16 b32 words
// = 32 fp16 halves of K. 64 mainloop iterations cover K=2048.
constexpr int GST = 4;
constexpr int STAGE_W = 128 * 16;         // 2048 words per (matrix,stage)
constexpr int GEMM_SMEM = 2 * GST * STAGE_W * 4 + 128 * 4 * 4;  // 67584 B
}

// ---------------- scratch (static device globals; no allocation allowed) ---
__device__ __half g_xconv[(size_t)Bb * Tt * Cc];
__device__ __half g_q   [(size_t)Bb * Tt * Cc];
__device__ __half g_k   [(size_t)Bb * Tt * Cc];
__device__ __half g_v   [(size_t)Bb * Tt * Cc];
__device__ __half g_gate[(size_t)Bb * Tt * Cc];
__device__ __half g_att [(size_t)Bb * Tt * Cc];
__device__ float  g_y   [(size_t)Bb * Tt * Cc];      // fp32 pre-LN output
__device__ __half g_xt  [(size_t)Bb * Tt * Cc];      // fp16-rounded x
__device__ __half g_Wqt [(size_t)Cc * Cc];
__device__ __half g_Wkt [(size_t)Cc * Cc];
__device__ __half g_Wvt [(size_t)Cc * Cc];
__device__ __half g_Wot [(size_t)Cc * Cc];
__device__ __half g_Wgt [(size_t)Cc * Cc];
__device__ float  g_F    [(size_t)Bb * Hh * NCHUNK * DhD];
__device__ float  g_carry[(size_t)Bb * Hh * NCHUNK * DhD];

// ---------------- helpers --------------------------------------------------
__device__ __forceinline__ uint32_t pack_h2(float a, float b) {
    __half2 h = __floats2half2_rn(a, b);
    return *reinterpret_cast<uint32_t*>(&h);
}
__device__ __forceinline__ float2 unpack_h2(uint32_t u) {
    return __half22float2(*reinterpret_cast<__half2*>(&u));
}

__device__ __forceinline__ void mma_f16(float& d0, float& d1, float& d2, float& d3,
                                        uint32_t a0, uint32_t a1, uint32_t a2, uint32_t a3,
                                        uint32_t b0, uint32_t b1) {
    asm volatile(
        "mma.sync.aligned.m16n8k16.row.col.f32.f16.f16.f32 "
        "{%0,%1,%2,%3}, {%4,%5,%6,%7}, {%8,%9}, {%0,%1,%2,%3};\n"
        : "+f"(d0), "+f"(d1), "+f"(d2), "+f"(d3)
        : "r"(a0), "r"(a1), "r"(a2), "r"(a3), "r"(b0), "r"(b1));
}

#define LDMATRIX_X4(r0, r1, r2, r3, addr) \
    asm volatile("ldmatrix.sync.aligned.m8n8.x4.shared.b16 {%0,%1,%2,%3}, [%4];" \
                 : "=r"(r0), "=r"(r1), "=r"(r2), "=r"(r3) : "r"(addr))

// ---------------- 0) fp16 conversion of the 5 weight matrices (one launch) --
__global__ void cvt5_f16_kernel(const float* __restrict__ w0, __half* __restrict__ o0,
                                const float* __restrict__ w1, __half* __restrict__ o1,
                                const float* __restrict__ w2, __half* __restrict__ o2,
                                const float* __restrict__ w3, __half* __restrict__ o3,
                                const float* __restrict__ w4, __half* __restrict__ o4) {
    const int seg = blockIdx.x >> 11;                 // 2048 blocks per weight
    const int i   = (blockIdx.x & 2047) * 256 + threadIdx.x;  // 8-elem group idx
    const float* in;
    __half* out;
    switch (seg) {
        case 0: in = w0; out = o0; break;
        case 1: in = w1; out = o1; break;
        case 2: in = w2; out = o2; break;
        case 3: in = w3; out = o3; break;
        default: in = w4; out = o4; break;
    }
    float4 v0 = reinterpret_cast<const float4*>(in)[i * 2];
    float4 v1 = reinterpret_cast<const float4*>(in)[i * 2 + 1];
    uint4 pk;
    pk.x = pack_h2(v0.x, v0.y);
    pk.y = pack_h2(v0.z, v0.w);
    pk.z = pack_h2(v1.x, v1.y);
    pk.w = pack_h2(v1.z, v1.w);
    reinterpret_cast<uint4*>(out)[i] = pk;
}

// ---------------- 1) causal depthwise conv (K=4) + SiLU + x fp16 side-out ---
__global__ void conv_silu_kernel(const float* __restrict__ x,
                                 const float* __restrict__ w,
                                 const float* __restrict__ bias) {
    int vid = blockIdx.x * blockDim.x + threadIdx.x;    // over B*T*C/4
    int cq  = vid & (Cc / 4 - 1);                       // channel quad
    int bt  = vid >> 9;                                 // /(2048/4)
    int t   = bt & (Tt - 1);
    int c   = cq * 4;

    const float4* x4 = reinterpret_cast<const float4*>(x);
    int base = (bt - t) * (Cc / 4) + cq;                // b*T*C/4 + cq

    float4 wr0 = reinterpret_cast<const float4*>(w)[c + 0];
    float4 wr1 = reinterpret_cast<const float4*>(w)[c + 1];
    float4 wr2 = reinterpret_cast<const float4*>(w)[c + 2];
    float4 wr3 = reinterpret_cast<const float4*>(w)[c + 3];
    float4 bb  = reinterpret_cast<const float4*>(bias)[cq];

    float4 a = bb;
    float4 xt3;
    #pragma unroll
    for (int j = 0; j < 4; j++) {
        int tt = t - 3 + j;
        if (tt >= 0) {
            float4 xv = x4[base + tt * (Cc / 4)];
            if (j == 3) xt3 = xv;
            float wj0 = (&wr0.x)[j], wj1 = (&wr1.x)[j], wj2 = (&wr2.x)[j], wj3 = (&wr3.x)[j];
            a.x = fmaf(xv.x, wj0, a.x);
            a.y = fmaf(xv.y, wj1, a.y);
            a.z = fmaf(xv.z, wj2, a.z);
            a.w = fmaf(xv.w, wj3, a.w);
        }
    }

    uint2 sc;
    sc.x = pack_h2(a.x / (1.0f + expf(-a.x)), a.y / (1.0f + expf(-a.y)));
    sc.y = pack_h2(a.z / (1.0f + expf(-a.z)), a.w / (1.0f + expf(-a.w)));
    reinterpret_cast<uint2*>(g_xconv)[vid] = sc;

    uint2 xr;
    xr.x = pack_h2(xt3.x, xt3.y);
    xr.y = pack_h2(xt3.z, xt3.w);
    reinterpret_cast<uint2*>(g_xt)[vid] = xr;
}

// ---------------- 2) FP16 GEMM tile body (4-stage pipeline, ldmatrix) -------
// Computes one 128x128 tile of Out = A[M,2048] * W[128-col slab]^T, fp16 in,
// fp32 accumulate. OutT = __half (qkvg) or float (y).
// mode 0: plain.  mode 1: sigmoid(out + bias[col]).  mode 2: per-row l2norm.
// Mainloop split into hot phase (unconditional wait/prefetch) + 3-iter drain.
// smem layout per (matrix,stage): 128 rows x 16 words, XOR-swizzled chunks:
//   word(row,w) at row*16 + (((w>>2) ^ ((row>>1)&3))<<2) + (w&3)
template <typename OutT>
__device__ __forceinline__
void gemm_tile_body(const __half* __restrict__ A, const __half* __restrict__ W,
                    OutT* __restrict__ Out, const float* __restrict__ bias,
                    int mode, int bm, int bn) {
    constexpr int BM = 128;
    constexpr int KH = 32;                // K halves per stage
    constexpr int KCH = Cc / KH;          // 64 iterations
    constexpr int N = Cc;

    extern __shared__ uint32_t dyn[];
    float* red = (float*)(dyn + 2 * GST * STAGE_W);  // 128*4 floats

    const int tid  = threadIdx.x;
    const int warp = tid >> 5, lane = tid & 31;
    const int gid  = lane >> 2, tg = lane & 3;
    const int wm   = warp & 1;       // 0..1  -> 64-row slab
    const int wn   = warp >> 1;      // 0..3  -> 32-col slab

    const int lr = tid >> 2;         // 0..63  (loader row)
    const int lc = tid & 3;          // chunk 0..3 (8 halves each)

    uint32_t sA = (uint32_t)__cvta_generic_to_shared(dyn);
    uint32_t sB = sA + (uint32_t)(GST * STAGE_W) * 4u;

    // ---- per-lane ldmatrix byte offsets within a stage (loop-invariant) ----
    const int lq  = lane >> 3;       // matrix quad 0..3
    const int lr8 = lane & 7;
    uint32_t aoff[2][4];             // [half][mt]
    uint32_t boff[2][2];             // [half][ntp]
    #pragma unroll
    for (int half = 0; half < 2; half++) {
        #pragma unroll
        for (int mt = 0; mt < 4; mt++) {
            int row   = wm * 64 + mt * 16 + (lq & 1) * 8 + lr8;
            int sw    = (row >> 1) & 3;
            int chunk = half * 2 + (lq >> 1);
            aoff[half][mt] = (uint32_t)(row * 64 + ((chunk ^ sw) << 4));
        }
        #pragma unroll
        for (int ntp = 0; ntp < 2; ntp++) {
            int col   = wn * 32 + (2 * ntp + (lq >> 1)) * 8 + lr8;
            int sw    = (col >> 1) & 3;
            int chunk = half * 2 + (lq & 1);
            boff[half][ntp] = (uint32_t)(col * 64 + ((chunk ^ sw) << 4));
        }
    }

    auto issue = [&](int s, int k0) {   // k0 in halves
        #pragma unroll
        for (int r = 0; r < 2; r++) {
            int row = lr + r * 64;
            int sw  = (row >> 1) & 3;
            uint32_t off = (uint32_t)(s * BM * 16 + row * 16 + ((lc ^ sw) << 2)) * 4u;
            const __half* gA = A + (size_t)(bm + row) * Cc + k0 + lc * 8;
            asm volatile("cp.async.cg.shared.global [%0], [%1], 16;\n"
                         :: "r"(sA + off), "l"(gA));
            const __half* gB = W + (size_t)(bn + row) * Cc + k0 + lc * 8;
            asm volatile("cp.async.cg.shared.global [%0], [%1], 16;\n"
                         :: "r"(sB + off), "l"(gB));
        }
        asm volatile("cp.async.commit_group;\n");
    };

    float acc[4][4][4] = {};

    auto compute = [&](int s) {
        const uint32_t stA = sA + (uint32_t)(s * STAGE_W) * 4u;
        const uint32_t stB = sB + (uint32_t)(s * STAGE_W) * 4u;
        uint32_t af[2][4][4], bf[2][4][2];
        #pragma unroll
        for (int half = 0; half < 2; half++) {
            #pragma unroll
            for (int mt = 0; mt < 4; mt++)
                LDMATRIX_X4(af[half][mt][0], af[half][mt][1],
                            af[half][mt][2], af[half][mt][3],
                            stA + aoff[half][mt]);
            #pragma unroll
            for (int ntp = 0; ntp < 2; ntp++)
                LDMATRIX_X4(bf[half][2 * ntp][0],     bf[half][2 * ntp][1],
                            bf[half][2 * ntp + 1][0], bf[half][2 * ntp + 1][1],
                            stB + boff[half][ntp]);
        }
        #pragma unroll
        for (int half = 0; half < 2; half++)
            #pragma unroll
            for (int mt = 0; mt < 4; mt++)
                #pragma unroll
                for (int nt = 0; nt < 4; nt++)
                    mma_f16(acc[mt][nt][0], acc[mt][nt][1], acc[mt][nt][2], acc[mt][nt][3],
                            af[half][mt][0], af[half][mt][1], af[half][mt][2], af[half][mt][3],
                            bf[half][nt][0], bf[half][nt][1]);
    };

    issue(0, 0);
    issue(1, KH);
    issue(2, 2 * KH);

    // hot phase: i = 0 .. KCH-4 — unconditional wait + prefetch
    int s = 0;
    for (int i = 0; i < KCH - 3; i++) {
        asm volatile("cp.async.wait_group 2;\n" ::: "memory");
        __syncthreads();
        int s2 = s + 3; if (s2 >= GST) s2 -= GST;
        issue(s2, (i + 3) * KH);
        compute(s);
        s++; if (s >= GST) s = 0;
    }
    // drain: last 3 stages, no prefetch
    asm volatile("cp.async.wait_group 2;\n" ::: "memory");
    __syncthreads();
    compute(s); s++; if (s >= GST) s = 0;
    asm volatile("cp.async.wait_group 1;\n" ::: "memory");
    __syncthreads();
    compute(s); s++; if (s >= GST) s = 0;
    asm volatile("cp.async.wait_group 0;\n" ::: "memory");
    __syncthreads();
    compute(s);

    // ---- fused l2norm over the 128-col tile (mode 2, tile == one head) -----
    if (mode == 2) {
        __syncthreads();
        float invLo[4], invHi[4];
        #pragma unroll
        for (int mt = 0; mt < 4; mt++) {
            float slo = 0.0f, shi = 0.0f;
            #pragma unroll
            for (int nt = 0; nt < 4; nt++) {
                slo = fmaf(acc[mt][nt][0], acc[mt][nt][0], slo);
                slo = fmaf(acc[mt][nt][1], acc[mt][nt][1], slo);
                shi = fmaf(acc[mt][nt][2], acc[mt][nt][2], shi);
                shi = fmaf(acc[mt][nt][3], acc[mt][nt][3], shi);
            }
            slo += __shfl_xor_sync(0xffffffffu, slo, 1);
            slo += __shfl_xor_sync(0xffffffffu, slo, 2);
            shi += __shfl_xor_sync(0xffffffffu, shi, 1);
            shi += __shfl_xor_sync(0xffffffffu, shi, 2);
            if (tg == 0) {
                int r = wm * 64 + mt * 16 + gid;
                red[r * 4 + wn]       = slo;
                red[(r + 8) * 4 + wn] = shi;
            }
        }
        __syncthreads();
        #pragma unroll
        for (int mt = 0; mt < 4; mt++) {
            int r = wm * 64 + mt * 16 + gid;
            float slo = red[r * 4 + 0] + red[r * 4 + 1] + red[r * 4 + 2] + red[r * 4 + 3];
            float shi = red[(r + 8) * 4 + 0] + red[(r + 8) * 4 + 1]
                      + red[(r + 8) * 4 + 2] + red[(r + 8) * 4 + 3];
            invLo[mt] = 1.0f / fmaxf(sqrtf(slo), 1e-12f);
            invHi[mt] = 1.0f / fmaxf(sqrtf(shi), 1e-12f);
        }
        #pragma unroll
        for (int mt = 0; mt < 4; mt++)
            #pragma unroll
            for (int nt = 0; nt < 4; nt++) {
                acc[mt][nt][0] *= invLo[mt];
                acc[mt][nt][1] *= invLo[mt];
                acc[mt][nt][2] *= invHi[mt];
                acc[mt][nt][3] *= invHi[mt];
            }
    }

    // epilogue stores
    #pragma unroll
    for (int mt = 0; mt < 4; mt++) {
        #pragma unroll
        for (int nt = 0; nt < 4; nt++) {
            int row = bm + wm * 64 + mt * 16 + gid;
            int col = bn + wn * 32 + nt * 8 + tg * 2;
            float v0 = acc[mt][nt][0], v1 = acc[mt][nt][1];
            float v2 = acc[mt][nt][2], v3 = acc[mt][nt][3];
            if (mode == 1) {
                float b0 = bias[col], b1 = bias[col + 1];
                v0 = 1.0f / (1.0f + expf(-(v0 + b0)));
                v1 = 1.0f / (1.0f + expf(-(v1 + b1)));
                v2 = 1.0f / (1.0f + expf(-(v2 + b0)));
                v3 = 1.0f / (1.0f + expf(-(v3 + b1)));
            }
            if constexpr (sizeof(OutT) == 2) {
                *reinterpret_cast<uint32_t*>(
                    (__half*)Out + (size_t)row * N + col)       = pack_h2(v0, v1);
                *reinterpret_cast<uint32_t*>(
                    (__half*)Out + (size_t)(row + 8) * N + col) = pack_h2(v2, v3);
            } else {
                *reinterpret_cast<float2*>(
                    (float*)Out + (size_t)row * N + col)        = make_float2(v0, v1);
                *reinterpret_cast<float2*>(
                    (float*)Out + (size_t)(row + 8) * N + col)  = make_float2(v2, v3);
            }
        }
    }
}

// Combined q/k/v/gate projection: one launch, 64 column-tiles x 128 row-tiles.
// seg = blockIdx.x>>4: 0=q(mode2) 1=k(mode2) 2=v(mode0) 3=gate(mode1, A=xconv)
__global__ __launch_bounds__(256, 2)
void gemm_qkvg_kernel(const float* __restrict__ gate_b) {
    const int seg = blockIdx.x >> 4;
    const int bn  = (blockIdx.x & 15) * 128;
    const int bm  = blockIdx.y * 128;

    const __half* A;
    const __half* W;
    __half* Out;
    int mode;
    switch (seg) {
        case 0:  A = g_xt;    W = g_Wqt; Out = g_q;    mode = 2; break;
        case 1:  A = g_xt;    W = g_Wkt; Out = g_k;    mode = 2; break;
        case 2:  A = g_xt;    W = g_Wvt; Out = g_v;    mode = 0; break;
        default: A = g_xconv; W = g_Wgt; Out = g_gate; mode = 1; break;
    }
    gemm_tile_body<__half>(A, W, Out, gate_b, mode, bm, bn);
}

// Output projection: y = att * Wo^T (mode 0, fp32 out for LayerNorm)
__global__ __launch_bounds__(256, 2)
void gemm_out_kernel() {
    gemm_tile_body<float>(g_att, g_Wot, g_y, nullptr, 0, blockIdx.y * 128, blockIdx.x * 128);
}

// ---------------- 4) chunked decayed scan (fp16 in, fp32 math) -------------
__global__ void scan_pass1(const __half* __restrict__ k, const __half* __restrict__ v,
                           const float* __restrict__ gamma) {
    int wid  = threadIdx.x >> 5, lane = threadIdx.x & 31;
    int blk  = blockIdx.x * 4 + wid;          // 0..4095
    int c    = blk & (NCHUNK - 1);
    int bh   = blk >> 6;
    int h    = bh & (Hh - 1);
    int b    = bh >> 4;
    float g  = gamma[h];
    const uint2* k2 = reinterpret_cast<const uint2*>(k);
    const uint2* v2 = reinterpret_cast<const uint2*>(v);
    size_t idx = ((size_t)(b * Tt + c * LCH) * Cc + h * DhD) / 4 + lane;
    float4 S = make_float4(0.f, 0.f, 0.f, 0.f);
    #pragma unroll 4
    for (int i = 0; i < LCH; i++) {
        uint2 ku = k2[idx], vu = v2[idx];
        float2 k0 = unpack_h2(ku.x), k1 = unpack_h2(ku.y);
        float2 va = unpack_h2(vu.x), vb = unpack_h2(vu.y);
        S.x = fmaf(g, S.x, k0.x * va.x);
        S.y = fmaf(g, S.y, k0.y * va.y);
        S.z = fmaf(g, S.z, k1.x * vb.x);
        S.w = fmaf(g, S.w, k1.y * vb.y);
        idx += Cc / 4;
    }
    reinterpret_cast<float4*>(g_F)[((size_t)bh * NCHUNK + c) * (DhD / 4) + lane] = S;
}

__global__ void scan_pass2(const float* __restrict__ gamma) {
    int tid = blockIdx.x * blockDim.x + threadIdx.x;   // over Bb*Hh*DhD/4 = 2048
    int d4  = tid & (DhD / 4 - 1);
    int bh  = tid >> 5;
    int h   = bh & (Hh - 1);
    float g  = gamma[h];
    float gL = powf(g, (float)LCH);     // exact 1.0 for gamma=1 head
    const float4* F4 = reinterpret_cast<const float4*>(g_F);
    float4* C4       = reinterpret_cast<float4*>(g_carry);
    float4 carry = make_float4(0.f, 0.f, 0.f, 0.f);
    for (int c = 0; c < NCHUNK; c++) {
        size_t o = ((size_t)bh * NCHUNK + c) * (DhD / 4) + d4;
        C4[o] = carry;
        float4 f = F4[o];
        carry.x = fmaf(gL, carry.x, f.x);
        carry.y = fmaf(gL, carry.y, f.y);
        carry.z = fmaf(gL, carry.z, f.z);
        carry.w = fmaf(gL, carry.w, f.w);
    }
}

__global__ void scan_pass3(const __half* __restrict__ k, const __half* __restrict__ v,
                           const __half* __restrict__ q, const __half* __restrict__ gate,
                           const float* __restrict__ gamma) {
    int wid  = threadIdx.x >> 5, lane = threadIdx.x & 31;
    int blk  = blockIdx.x * 4 + wid;
    int c    = blk & (NCHUNK - 1);
    int bh   = blk >> 6;
    int h    = bh & (Hh - 1);
    int b    = bh >> 4;
    float g  = gamma[h];
    const uint2* k2 = reinterpret_cast<const uint2*>(k);
    const uint2* v2 = reinterpret_cast<const uint2*>(v);
    const uint2* q2 = reinterpret_cast<const uint2*>(q);
    const uint2* g2 = reinterpret_cast<const uint2*>(gate);
    uint2* a2       = reinterpret_cast<uint2*>(g_att);   // 4 halves per slot
    float4 S = reinterpret_cast<const float4*>(g_carry)
                   [((size_t)bh * NCHUNK + c) * (DhD / 4) + lane];
    size_t idx = ((size_t)(b * Tt + c * LCH) * Cc + h * DhD) / 4 + lane;
    #pragma unroll 4
    for (int i = 0; i < LCH; i++) {
        uint2 ku = k2[idx], vu = v2[idx];
        float2 k0 = unpack_h2(ku.x), k1 = unpack_h2(ku.y);
        float2 va = unpack_h2(vu.x), vb = unpack_h2(vu.y);
        S.x = fmaf(g, S.x, k0.x * va.x);
        S.y = fmaf(g, S.y, k0.y * va.y);
        S.z = fmaf(g, S.z, k1.x * vb.x);
        S.w = fmaf(g, S.w, k1.y * vb.y);
        uint2 gu = g2[idx], qu = q2[idx];
        float2 g0 = unpack_h2(gu.x), g1 = unpack_h2(gu.y);
        float2 q0 = unpack_h2(qu.x), q1 = unpack_h2(qu.y);
        uint2 o;
        o.x = pack_h2(g0.x * S.x * q0.x, g0.y * S.y * q0.y);
        o.y = pack_h2(g1.x * S.z * q1.x, g1.y * S.w * q1.y);
        a2[idx] = o;
        idx += Cc / 4;
    }
}

// ---------------- 5) LayerNorm over C=2048 (fp32 in/out) --------------------
__global__ __launch_bounds__(256)
void ln_kernel(const float* __restrict__ y, const float* __restrict__ lw,
               const float* __restrict__ lb, float* __restrict__ out) {
    int row = blockIdx.x;
    int tid = threadIdx.x;
    const float4* yr = reinterpret_cast<const float4*>(y + (size_t)row * Cc);
    float4* orow     = reinterpret_cast<float4*>(out + (size_t)row * Cc);

    float4 v0 = yr[tid];
    float4 v1 = yr[tid + 256];
    float sum = v0.x + v0.y + v0.z + v0.w + v1.x + v1.y + v1.z + v1.w;
    float sq  = v0.x * v0.x + v0.y * v0.y + v0.z * v0.z + v0.w * v0.w
              + v1.x * v1.x + v1.y * v1.y + v1.z * v1.z + v1.w * v1.w;

    #pragma unroll
    for (int o = 16; o; o >>= 1) {
        sum += __shfl_xor_sync(0xffffffffu, sum, o);
        sq  += __shfl_xor_sync(0xffffffffu, sq, o);
    }
    __shared__ float ssum[8], ssq[8];
    __shared__ float s_mu, s_inv;
    int warp = tid >> 5, lane = tid & 31;
    if (lane == 0) { ssum[warp] = sum; ssq[warp] = sq; }
    __syncthreads();
    if (tid == 0) {
        float ts = 0.0f, tq = 0.0f;
        #pragma unroll
        for (int i = 0; i < 8; i++) { ts += ssum[i]; tq += ssq[i]; }
        float mu  = ts / (float)Cc;
        float var = tq / (float)Cc - mu * mu;
        s_mu  = mu;
        s_inv = rsqrtf(var + 1e-5f);
    }
    __syncthreads();
    float mu = s_mu, inv = s_inv;

    const float4 w0 = reinterpret_cast<const float4*>(lw)[tid];
    const float4 w1 = reinterpret_cast<const float4*>(lw)[tid + 256];
    const float4 b0 = reinterpret_cast<const float4*>(lb)[tid];
    const float4 b1 = reinterpret_cast<const float4*>(lb)[tid + 256];

    float4 o0, o1;
    o0.x = (v0.x - mu) * inv * w0.x + b0.x;
    o0.y = (v0.y - mu) * inv * w0.y + b0.y;
    o0.z = (v0.z - mu) * inv * w0.z + b0.z;
    o0.w = (v0.w - mu) * inv * w0.w + b0.w;
    o1.x = (v1.x - mu) * inv * w1.x + b1.x;
    o1.y = (v1.y - mu) * inv * w1.y + b1.y;
    o1.z = (v1.z - mu) * inv * w1.z + b1.z;
    o1.w = (v1.w - mu) * inv * w1.w + b1.w;
    orow[tid]       = o0;
    orow[tid + 256] = o1;
}

// ---------------- host orchestration ---------------------------------------
extern "C" void kernel_launch(void* const* d_in, const int* in_sizes, int n_in,
                              void* d_out, int out_size) {
    (void)in_sizes; (void)n_in; (void)out_size;
    const float* x      = (const float*)d_in[0];
    const float* Wq     = (const float*)d_in[1];
    const float* Wk     = (const float*)d_in[2];
    const float* Wv     = (const float*)d_in[3];
    const float* Wo     = (const float*)d_in[4];
    const float* conv_w = (const float*)d_in[5];
    const float* conv_b = (const float*)d_in[6];
    const float* gate_w = (const float*)d_in[7];
    const float* gate_b = (const float*)d_in[8];
    const float* ln_w   = (const float*)d_in[9];
    const float* ln_b   = (const float*)d_in[10];
    const float* gamma  = (const float*)d_in[11];

    __half *p_q, *p_k, *p_v, *p_gate;
    float  *p_y;
    __half *p_Wqt, *p_Wkt, *p_Wvt, *p_Wot, *p_Wgt;
    cudaGetSymbolAddress((void**)&p_q, g_q);
    cudaGetSymbolAddress((void**)&p_k, g_k);
    cudaGetSymbolAddress((void**)&p_v, g_v);
    cudaGetSymbolAddress((void**)&p_gate, g_gate);
    cudaGetSymbolAddress((void**)&p_y, g_y);
    cudaGetSymbolAddress((void**)&p_Wqt, g_Wqt);
    cudaGetSymbolAddress((void**)&p_Wkt, g_Wkt);
    cudaGetSymbolAddress((void**)&p_Wvt, g_Wvt);
    cudaGetSymbolAddress((void**)&p_Wot, g_Wot);
    cudaGetSymbolAddress((void**)&p_Wgt, g_Wgt);

    // allow 66KB dynamic smem on the GEMM kernels (idempotent)
    cudaFuncSetAttribute(gemm_qkvg_kernel, cudaFuncAttributeMaxDynamicSharedMemorySize, GEMM_SMEM);
    cudaFuncSetAttribute(gemm_out_kernel,  cudaFuncAttributeMaxDynamicSharedMemorySize, GEMM_SMEM);

    // 0) convert the 5 weight matrices to fp16 in one launch
    const int wBlocks = (Cc * Cc) / 2048;  // 2048 blocks per weight
    cvt5_f16_kernel<<<5 * wBlocks, 256>>>(Wq, p_Wqt, Wk, p_Wkt, Wv, p_Wvt,
                                          Wo, p_Wot, gate_w, p_Wgt);

    // 1) depthwise conv + SiLU (float4); also emits fp16 x (g_xt)
    conv_silu_kernel<<<(Mrows * Cc / 4) / 256, 256>>>(x, conv_w, conv_b);

    // 2) all four projections in ONE launch (q, k, v, gate) — fp16 outputs
    dim3 qgrid(64, Mrows / 128);   // 64 col-tiles (4 segs x 16), 128 row-tiles
    gemm_qkvg_kernel<<<qgrid, 256, GEMM_SMEM>>>(gate_b);

    // 3) decayed scan (chunked, exact); fp16 inputs, fp32 recurrence
    scan_pass1<<<Bb * Hh * NCHUNK / 4, 128>>>(p_k, p_v, gamma);
    scan_pass2<<<16, 128>>>(gamma);
    scan_pass3<<<Bb * Hh * NCHUNK / 4, 128>>>(p_k, p_v, p_q, p_gate, gamma);

    // 4) output projection (fp32 y) + LayerNorm
    dim3 ogrid(Cc / 128, Mrows / 128);   // (16, 128)
    gemm_out_kernel<<<ogrid, 256, GEMM_SMEM>>>();
    ln_kernel<<<Mrows, 256>>>(p_y, ln_w, ln_b, (float*)d_out);
}

// round 17
// speedup vs baseline: 1.1349x; 1.0456x over previous
#include <cuda_runtime.h>
#include <cuda_fp16.h>
#include <cstdint>
#include <cstdio>

// Problem constants
namespace {
constexpr int Bb = 4, Tt = 4096, Cc = 2048, Hh = 16, DhD = 128;
constexpr int Mrows = Bb * Tt;            // 16384
constexpr int NCHUNK = 64;                // scan chunks
constexpr int LCH = Tt / NCHUNK;          // 64 steps per chunk
// GEMM pipeline: 4 stages, prefetch distance 3. One stage row = 16 b32 words
// = 32 fp16 halves of K. 64 mainloop iterations cover K=2048.
constexpr int GST = 4;
constexpr int STAGE_W = 128 * 16;         // 2048 words per (matrix,stage)
constexpr int GEMM_SMEM = 2 * GST * STAGE_W * 4 + 128 * 4 * 4;  // 67584 B
}

// ---------------- scratch (static device globals; no allocation allowed) ---
__device__ __half g_xconv[(size_t)Bb * Tt * Cc];
__device__ __half g_q   [(size_t)Bb * Tt * Cc];
__device__ __half g_k   [(size_t)Bb * Tt * Cc];
__device__ __half g_v   [(size_t)Bb * Tt * Cc];
__device__ __half g_gate[(size_t)Bb * Tt * Cc];
__device__ __half g_att [(size_t)Bb * Tt * Cc];
__device__ float  g_y   [(size_t)Bb * Tt * Cc];      // fp32 pre-LN output
__device__ __half g_xt  [(size_t)Bb * Tt * Cc];      // fp16-rounded x
__device__ __half g_Wqt [(size_t)Cc * Cc];
__device__ __half g_Wkt [(size_t)Cc * Cc];
__device__ __half g_Wvt [(size_t)Cc * Cc];
__device__ __half g_Wot [(size_t)Cc * Cc];
__device__ __half g_Wgt [(size_t)Cc * Cc];
__device__ float  g_F    [(size_t)Bb * Hh * NCHUNK * DhD];
__device__ float  g_carry[(size_t)Bb * Hh * NCHUNK * DhD];

// ---------------- helpers --------------------------------------------------
__device__ __forceinline__ uint32_t pack_h2(float a, float b) {
    __half2 h = __floats2half2_rn(a, b);
    return *reinterpret_cast<uint32_t*>(&h);
}
__device__ __forceinline__ float2 unpack_h2(uint32_t u) {
    return __half22float2(*reinterpret_cast<__half2*>(&u));
}

__device__ __forceinline__ void mma_f16(float& d0, float& d1, float& d2, float& d3,
                                        uint32_t a0, uint32_t a1, uint32_t a2, uint32_t a3,
                                        uint32_t b0, uint32_t b1) {
    asm volatile(
        "mma.sync.aligned.m16n8k16.row.col.f32.f16.f16.f32 "
        "{%0,%1,%2,%3}, {%4,%5,%6,%7}, {%8,%9}, {%0,%1,%2,%3};\n"
        : "+f"(d0), "+f"(d1), "+f"(d2), "+f"(d3)
        : "r"(a0), "r"(a1), "r"(a2), "r"(a3), "r"(b0), "r"(b1));
}

#define LDMATRIX_X4(r0, r1, r2, r3, addr) \
    asm volatile("ldmatrix.sync.aligned.m8n8.x4.shared.b16 {%0,%1,%2,%3}, [%4];" \
                 : "=r"(r0), "=r"(r1), "=r"(r2), "=r"(r3) : "r"(addr))

// ---------------- 0) fp16 conversion of the 5 weight matrices (one launch) --
__global__ void cvt5_f16_kernel(const float* __restrict__ w0, __half* __restrict__ o0,
                                const float* __restrict__ w1, __half* __restrict__ o1,
                                const float* __restrict__ w2, __half* __restrict__ o2,
                                const float* __restrict__ w3, __half* __restrict__ o3,
                                const float* __restrict__ w4, __half* __restrict__ o4) {
    const int seg = blockIdx.x >> 11;                 // 2048 blocks per weight
    const int i   = (blockIdx.x & 2047) * 256 + threadIdx.x;  // 8-elem group idx
    const float* in;
    __half* out;
    switch (seg) {
        case 0: in = w0; out = o0; break;
        case 1: in = w1; out = o1; break;
        case 2: in = w2; out = o2; break;
        case 3: in = w3; out = o3; break;
        default: in = w4; out = o4; break;
    }
    float4 v0 = reinterpret_cast<const float4*>(in)[i * 2];
    float4 v1 = reinterpret_cast<const float4*>(in)[i * 2 + 1];
    uint4 pk;
    pk.x = pack_h2(v0.x, v0.y);
    pk.y = pack_h2(v0.z, v0.w);
    pk.z = pack_h2(v1.x, v1.y);
    pk.w = pack_h2(v1.z, v1.w);
    reinterpret_cast<uint4*>(out)[i] = pk;
}

// ---------------- 1) causal depthwise conv (K=4) + SiLU, T-blocked (TB=4) ---
// Each thread: one channel quad, 4 consecutive timesteps. 7 x-row loads
// (zero-filled for t<0 — identical arithmetic to skipping), 4 outputs.
// Also emits fp16-rounded x (g_xt) from the tap-3 rows.
__global__ void conv_silu_kernel(const float* __restrict__ x,
                                 const float* __restrict__ w,
                                 const float* __restrict__ bias) {
    int vid = blockIdx.x * blockDim.x + threadIdx.x;    // over B*(T/4)*(C/4)
    int cq  = vid & (Cc / 4 - 1);                       // channel quad
    int bt4 = vid >> 9;                                 // b*(T/4)+t4
    int t4  = bt4 & (Tt / 4 - 1);
    int b   = bt4 >> 10;                                // T/4 = 1024
    int t0  = t4 * 4;
    int c   = cq * 4;

    const float4* x4 = reinterpret_cast<const float4*>(x);
    size_t rowBase = (size_t)b * Tt * (Cc / 4) + cq;

    float4 wr0 = reinterpret_cast<const float4*>(w)[c + 0];
    float4 wr1 = reinterpret_cast<const float4*>(w)[c + 1];
    float4 wr2 = reinterpret_cast<const float4*>(w)[c + 2];
    float4 wr3 = reinterpret_cast<const float4*>(w)[c + 3];
    float4 bb  = reinterpret_cast<const float4*>(bias)[cq];

    float4 xv[7];
    #pragma unroll
    for (int j = 0; j < 7; j++) {
        int tt = t0 - 3 + j;
        if (tt >= 0) xv[j] = x4[rowBase + (size_t)tt * (Cc / 4)];
        else         xv[j] = make_float4(0.f, 0.f, 0.f, 0.f);
    }

    uint2* xc2 = reinterpret_cast<uint2*>(g_xconv);
    uint2* xt2 = reinterpret_cast<uint2*>(g_xt);
    size_t outBase = (size_t)(b * Tt + t0) * (Cc / 4) + cq;

    #pragma unroll
    for (int i = 0; i < 4; i++) {           // output timestep t0+i
        float4 a = bb;
        #pragma unroll
        for (int j = 0; j < 4; j++) {       // tap j uses xv[i+j]
            float4 xvv = xv[i + j];
            a.x = fmaf(xvv.x, (&wr0.x)[j], a.x);
            a.y = fmaf(xvv.y, (&wr1.x)[j], a.y);
            a.z = fmaf(xvv.z, (&wr2.x)[j], a.z);
            a.w = fmaf(xvv.w, (&wr3.x)[j], a.w);
        }
        uint2 sc;
        sc.x = pack_h2(a.x / (1.0f + expf(-a.x)), a.y / (1.0f + expf(-a.y)));
        sc.y = pack_h2(a.z / (1.0f + expf(-a.z)), a.w / (1.0f + expf(-a.w)));
        xc2[outBase + (size_t)i * (Cc / 4)] = sc;

        float4 xr = xv[i + 3];              // x at t = t0+i
        uint2 xo;
        xo.x = pack_h2(xr.x, xr.y);
        xo.y = pack_h2(xr.z, xr.w);
        xt2[outBase + (size_t)i * (Cc / 4)] = xo;
    }
}

// ---------------- 2) FP16 GEMM tile body (4-stage pipeline, ldmatrix) -------
// Computes one 128x128 tile of Out = A[M,2048] * W[128-col slab]^T, fp16 in,
// fp32 accumulate. OutT = __half (qkvg) or float (y).
// mode 0: plain.  mode 1: sigmoid(out + bias[col]).  mode 2: per-row l2norm.
// Mainloop split into hot phase (unconditional wait/prefetch) + 3-iter drain.
// smem layout per (matrix,stage): 128 rows x 16 words, XOR-swizzled chunks:
//   word(row,w) at row*16 + (((w>>2) ^ ((row>>1)&3))<<2) + (w&3)
template <typename OutT>
__device__ __forceinline__
void gemm_tile_body(const __half* __restrict__ A, const __half* __restrict__ W,
                    OutT* __restrict__ Out, const float* __restrict__ bias,
                    int mode, int bm, int bn) {
    constexpr int BM = 128;
    constexpr int KH = 32;                // K halves per stage
    constexpr int KCH = Cc / KH;          // 64 iterations
    constexpr int N = Cc;

    extern __shared__ uint32_t dyn[];
    float* red = (float*)(dyn + 2 * GST * STAGE_W);  // 128*4 floats

    const int tid  = threadIdx.x;
    const int warp = tid >> 5, lane = tid & 31;
    const int gid  = lane >> 2, tg = lane & 3;
    const int wm   = warp & 1;       // 0..1  -> 64-row slab
    const int wn   = warp >> 1;      // 0..3  -> 32-col slab

    const int lr = tid >> 2;         // 0..63  (loader row)
    const int lc = tid & 3;          // chunk 0..3 (8 halves each)

    uint32_t sA = (uint32_t)__cvta_generic_to_shared(dyn);
    uint32_t sB = sA + (uint32_t)(GST * STAGE_W) * 4u;

    // ---- per-lane ldmatrix byte offsets within a stage (loop-invariant) ----
    const int lq  = lane >> 3;       // matrix quad 0..3
    const int lr8 = lane & 7;
    uint32_t aoff[2][4];             // [half][mt]
    uint32_t boff[2][2];             // [half][ntp]
    #pragma unroll
    for (int half = 0; half < 2; half++) {
        #pragma unroll
        for (int mt = 0; mt < 4; mt++) {
            int row   = wm * 64 + mt * 16 + (lq & 1) * 8 + lr8;
            int sw    = (row >> 1) & 3;
            int chunk = half * 2 + (lq >> 1);
            aoff[half][mt] = (uint32_t)(row * 64 + ((chunk ^ sw) << 4));
        }
        #pragma unroll
        for (int ntp = 0; ntp < 2; ntp++) {
            int col   = wn * 32 + (2 * ntp + (lq >> 1)) * 8 + lr8;
            int sw    = (col >> 1) & 3;
            int chunk = half * 2 + (lq & 1);
            boff[half][ntp] = (uint32_t)(col * 64 + ((chunk ^ sw) << 4));
        }
    }

    auto issue = [&](int s, int k0) {   // k0 in halves
        #pragma unroll
        for (int r = 0; r < 2; r++) {
            int row = lr + r * 64;
            int sw  = (row >> 1) & 3;
            uint32_t off = (uint32_t)(s * BM * 16 + row * 16 + ((lc ^ sw) << 2)) * 4u;
            const __half* gA = A + (size_t)(bm + row) * Cc + k0 + lc * 8;
            asm volatile("cp.async.cg.shared.global [%0], [%1], 16;\n"
                         :: "r"(sA + off), "l"(gA));
            const __half* gB = W + (size_t)(bn + row) * Cc + k0 + lc * 8;
            asm volatile("cp.async.cg.shared.global [%0], [%1], 16;\n"
                         :: "r"(sB + off), "l"(gB));
        }
        asm volatile("cp.async.commit_group;\n");
    };

    float acc[4][4][4] = {};

    auto compute = [&](int s) {
        const uint32_t stA = sA + (uint32_t)(s * STAGE_W) * 4u;
        const uint32_t stB = sB + (uint32_t)(s * STAGE_W) * 4u;
        uint32_t af[2][4][4], bf[2][4][2];
        #pragma unroll
        for (int half = 0; half < 2; half++) {
            #pragma unroll
            for (int mt = 0; mt < 4; mt++)
                LDMATRIX_X4(af[half][mt][0], af[half][mt][1],
                            af[half][mt][2], af[half][mt][3],
                            stA + aoff[half][mt]);
            #pragma unroll
            for (int ntp = 0; ntp < 2; ntp++)
                LDMATRIX_X4(bf[half][2 * ntp][0],     bf[half][2 * ntp][1],
                            bf[half][2 * ntp + 1][0], bf[half][2 * ntp + 1][1],
                            stB + boff[half][ntp]);
        }
        #pragma unroll
        for (int half = 0; half < 2; half++)
            #pragma unroll
            for (int mt = 0; mt < 4; mt++)
                #pragma unroll
                for (int nt = 0; nt < 4; nt++)
                    mma_f16(acc[mt][nt][0], acc[mt][nt][1], acc[mt][nt][2], acc[mt][nt][3],
                            af[half][mt][0], af[half][mt][1], af[half][mt][2], af[half][mt][3],
                            bf[half][nt][0], bf[half][nt][1]);
    };

    issue(0, 0);
    issue(1, KH);
    issue(2, 2 * KH);

    // hot phase: i = 0 .. KCH-4 — unconditional wait + prefetch
    int s = 0;
    for (int i = 0; i < KCH - 3; i++) {
        asm volatile("cp.async.wait_group 2;\n" ::: "memory");
        __syncthreads();
        int s2 = s + 3; if (s2 >= GST) s2 -= GST;
        issue(s2, (i + 3) * KH);
        compute(s);
        s++; if (s >= GST) s = 0;
    }
    // drain: last 3 stages, no prefetch
    asm volatile("cp.async.wait_group 2;\n" ::: "memory");
    __syncthreads();
    compute(s); s++; if (s >= GST) s = 0;
    asm volatile("cp.async.wait_group 1;\n" ::: "memory");
    __syncthreads();
    compute(s); s++; if (s >= GST) s = 0;
    asm volatile("cp.async.wait_group 0;\n" ::: "memory");
    __syncthreads();
    compute(s);

    // ---- fused l2norm over the 128-col tile (mode 2, tile == one head) -----
    if (mode == 2) {
        __syncthreads();
        float invLo[4], invHi[4];
        #pragma unroll
        for (int mt = 0; mt < 4; mt++) {
            float slo = 0.0f, shi = 0.0f;
            #pragma unroll
            for (int nt = 0; nt < 4; nt++) {
                slo = fmaf(acc[mt][nt][0], acc[mt][nt][0], slo);
                slo = fmaf(acc[mt][nt][1], acc[mt][nt][1], slo);
                shi = fmaf(acc[mt][nt][2], acc[mt][nt][2], shi);
                shi = fmaf(acc[mt][nt][3], acc[mt][nt][3], shi);
            }
            slo += __shfl_xor_sync(0xffffffffu, slo, 1);
            slo += __shfl_xor_sync(0xffffffffu, slo, 2);
            shi += __shfl_xor_sync(0xffffffffu, shi, 1);
            shi += __shfl_xor_sync(0xffffffffu, shi, 2);
            if (tg == 0) {
                int r = wm * 64 + mt * 16 + gid;
                red[r * 4 + wn]       = slo;
                red[(r + 8) * 4 + wn] = shi;
            }
        }
        __syncthreads();
        #pragma unroll
        for (int mt = 0; mt < 4; mt++) {
            int r = wm * 64 + mt * 16 + gid;
            float slo = red[r * 4 + 0] + red[r * 4 + 1] + red[r * 4 + 2] + red[r * 4 + 3];
            float shi = red[(r + 8) * 4 + 0] + red[(r + 8) * 4 + 1]
                      + red[(r + 8) * 4 + 2] + red[(r + 8) * 4 + 3];
            invLo[mt] = 1.0f / fmaxf(sqrtf(slo), 1e-12f);
            invHi[mt] = 1.0f / fmaxf(sqrtf(shi), 1e-12f);
        }
        #pragma unroll
        for (int mt = 0; mt < 4; mt++)
            #pragma unroll
            for (int nt = 0; nt < 4; nt++) {
                acc[mt][nt][0] *= invLo[mt];
                acc[mt][nt][1] *= invLo[mt];
                acc[mt][nt][2] *= invHi[mt];
                acc[mt][nt][3] *= invHi[mt];
            }
    }

    // epilogue stores
    #pragma unroll
    for (int mt = 0; mt < 4; mt++) {
        #pragma unroll
        for (int nt = 0; nt < 4; nt++) {
            int row = bm + wm * 64 + mt * 16 + gid;
            int col = bn + wn * 32 + nt * 8 + tg * 2;
            float v0 = acc[mt][nt][0], v1 = acc[mt][nt][1];
            float v2 = acc[mt][nt][2], v3 = acc[mt][nt][3];
            if (mode == 1) {
                float b0 = bias[col], b1 = bias[col + 1];
                v0 = 1.0f / (1.0f + expf(-(v0 + b0)));
                v1 = 1.0f / (1.0f + expf(-(v1 + b1)));
                v2 = 1.0f / (1.0f + expf(-(v2 + b0)));
                v3 = 1.0f / (1.0f + expf(-(v3 + b1)));
            }
            if constexpr (sizeof(OutT) == 2) {
                *reinterpret_cast<uint32_t*>(
                    (__half*)Out + (size_t)row * N + col)       = pack_h2(v0, v1);
                *reinterpret_cast<uint32_t*>(
                    (__half*)Out + (size_t)(row + 8) * N + col) = pack_h2(v2, v3);
            } else {
                *reinterpret_cast<float2*>(
                    (float*)Out + (size_t)row * N + col)        = make_float2(v0, v1);
                *reinterpret_cast<float2*>(
                    (float*)Out + (size_t)(row + 8) * N + col)  = make_float2(v2, v3);
            }
        }
    }
}

// Combined q/k/v/gate projection: one launch, 64 column-tiles x 128 row-tiles.
// seg = blockIdx.x>>4: 0=q(mode2) 1=k(mode2) 2=v(mode0) 3=gate(mode1, A=xconv)
__global__ __launch_bounds__(256, 2)
void gemm_qkvg_kernel(const float* __restrict__ gate_b) {
    const int seg = blockIdx.x >> 4;
    const int bn  = (blockIdx.x & 15) * 128;
    const int bm  = blockIdx.y * 128;

    const __half* A;
    const __half* W;
    __half* Out;
    int mode;
    switch (seg) {
        case 0:  A = g_xt;    W = g_Wqt; Out = g_q;    mode = 2; break;
        case 1:  A = g_xt;    W = g_Wkt; Out = g_k;    mode = 2; break;
        case 2:  A = g_xt;    W = g_Wvt; Out = g_v;    mode = 0; break;
        default: A = g_xconv; W = g_Wgt; Out = g_gate; mode = 1; break;
    }
    gemm_tile_body<__half>(A, W, Out, gate_b, mode, bm, bn);
}

// Output projection: y = att * Wo^T (mode 0, fp32 out for LayerNorm)
__global__ __launch_bounds__(256, 2)
void gemm_out_kernel() {
    gemm_tile_body<float>(g_att, g_Wot, g_y, nullptr, 0, blockIdx.y * 128, blockIdx.x * 128);
}

// ---------------- 4) chunked decayed scan (fp16 in, fp32 math) -------------
__global__ void scan_pass1(const __half* __restrict__ k, const __half* __restrict__ v,
                           const float* __restrict__ gamma) {
    int wid  = threadIdx.x >> 5, lane = threadIdx.x & 31;
    int blk  = blockIdx.x * 4 + wid;          // 0..4095
    int c    = blk & (NCHUNK - 1);
    int bh   = blk >> 6;
    int h    = bh & (Hh - 1);
    int b    = bh >> 4;
    float g  = gamma[h];
    const uint2* k2 = reinterpret_cast<const uint2*>(k);
    const uint2* v2 = reinterpret_cast<const uint2*>(v);
    size_t idx = ((size_t)(b * Tt + c * LCH) * Cc + h * DhD) / 4 + lane;
    float4 S = make_float4(0.f, 0.f, 0.f, 0.f);
    #pragma unroll 4
    for (int i = 0; i < LCH; i++) {
        uint2 ku = k2[idx], vu = v2[idx];
        float2 k0 = unpack_h2(ku.x), k1 = unpack_h2(ku.y);
        float2 va = unpack_h2(vu.x), vb = unpack_h2(vu.y);
        S.x = fmaf(g, S.x, k0.x * va.x);
        S.y = fmaf(g, S.y, k0.y * va.y);
        S.z = fmaf(g, S.z, k1.x * vb.x);
        S.w = fmaf(g, S.w, k1.y * vb.y);
        idx += Cc / 4;
    }
    reinterpret_cast<float4*>(g_F)[((size_t)bh * NCHUNK + c) * (DhD / 4) + lane] = S;
}

__global__ void scan_pass2(const float* __restrict__ gamma) {
    int tid = blockIdx.x * blockDim.x + threadIdx.x;   // over Bb*Hh*DhD/4 = 2048
    int d4  = tid & (DhD / 4 - 1);
    int bh  = tid >> 5;
    int h   = bh & (Hh - 1);
    float g  = gamma[h];
    float gL = powf(g, (float)LCH);     // exact 1.0 for gamma=1 head
    const float4* F4 = reinterpret_cast<const float4*>(g_F);
    float4* C4       = reinterpret_cast<float4*>(g_carry);
    float4 carry = make_float4(0.f, 0.f, 0.f, 0.f);
    for (int c = 0; c < NCHUNK; c++) {
        size_t o = ((size_t)bh * NCHUNK + c) * (DhD / 4) + d4;
        C4[o] = carry;
        float4 f = F4[o];
        carry.x = fmaf(gL, carry.x, f.x);
        carry.y = fmaf(gL, carry.y, f.y);
        carry.z = fmaf(gL, carry.z, f.z);
        carry.w = fmaf(gL, carry.w, f.w);
    }
}

__global__ void scan_pass3(const __half* __restrict__ k, const __half* __restrict__ v,
                           const __half* __restrict__ q, const __half* __restrict__ gate,
                           const float* __restrict__ gamma) {
    int wid  = threadIdx.x >> 5, lane = threadIdx.x & 31;
    int blk  = blockIdx.x * 4 + wid;
    int c    = blk & (NCHUNK - 1);
    int bh   = blk >> 6;
    int h    = bh & (Hh - 1);
    int b    = bh >> 4;
    float g  = gamma[h];
    const uint2* k2 = reinterpret_cast<const uint2*>(k);
    const uint2* v2 = reinterpret_cast<const uint2*>(v);
    const uint2* q2 = reinterpret_cast<const uint2*>(q);
    const uint2* g2 = reinterpret_cast<const uint2*>(gate);
    uint2* a2       = reinterpret_cast<uint2*>(g_att);   // 4 halves per slot
    float4 S = reinterpret_cast<const float4*>(g_carry)
                   [((size_t)bh * NCHUNK + c) * (DhD / 4) + lane];
    size_t idx = ((size_t)(b * Tt + c * LCH) * Cc + h * DhD) / 4 + lane;
    #pragma unroll 4
    for (int i = 0; i < LCH; i++) {
        uint2 ku = k2[idx], vu = v2[idx];
        float2 k0 = unpack_h2(ku.x), k1 = unpack_h2(ku.y);
        float2 va = unpack_h2(vu.x), vb = unpack_h2(vu.y);
        S.x = fmaf(g, S.x, k0.x * va.x);
        S.y = fmaf(g, S.y, k0.y * va.y);
        S.z = fmaf(g, S.z, k1.x * vb.x);
        S.w = fmaf(g, S.w, k1.y * vb.y);
        uint2 gu = g2[idx], qu = q2[idx];
        float2 g0 = unpack_h2(gu.x), g1 = unpack_h2(gu.y);
        float2 q0 = unpack_h2(qu.x), q1 = unpack_h2(qu.y);
        uint2 o;
        o.x = pack_h2(g0.x * S.x * q0.x, g0.y * S.y * q0.y);
        o.y = pack_h2(g1.x * S.z * q1.x, g1.y * S.w * q1.y);
        a2[idx] = o;
        idx += Cc / 4;
    }
}

// ---------------- 5) LayerNorm over C=2048 (fp32 in/out) --------------------
__global__ __launch_bounds__(256)
void ln_kernel(const float* __restrict__ y, const float* __restrict__ lw,
               const float* __restrict__ lb, float* __restrict__ out) {
    int row = blockIdx.x;
    int tid = threadIdx.x;
    const float4* yr = reinterpret_cast<const float4*>(y + (size_t)row * Cc);
    float4* orow     = reinterpret_cast<float4*>(out + (size_t)row * Cc);

    float4 v0 = yr[tid];
    float4 v1 = yr[tid + 256];
    float sum = v0.x + v0.y + v0.z + v0.w + v1.x + v1.y + v1.z + v1.w;
    float sq  = v0.x * v0.x + v0.y * v0.y + v0.z * v0.z + v0.w * v0.w
              + v1.x * v1.x + v1.y * v1.y + v1.z * v1.z + v1.w * v1.w;

    #pragma unroll
    for (int o = 16; o; o >>= 1) {
        sum += __shfl_xor_sync(0xffffffffu, sum, o);
        sq  += __shfl_xor_sync(0xffffffffu, sq, o);
    }
    __shared__ float ssum[8], ssq[8];
    __shared__ float s_mu, s_inv;
    int warp = tid >> 5, lane = tid & 31;
    if (lane == 0) { ssum[warp] = sum; ssq[warp] = sq; }
    __syncthreads();
    if (tid == 0) {
        float ts = 0.0f, tq = 0.0f;
        #pragma unroll
        for (int i = 0; i < 8; i++) { ts += ssum[i]; tq += ssq[i]; }
        float mu  = ts / (float)Cc;
        float var = tq / (float)Cc - mu * mu;
        s_mu  = mu;
        s_inv = rsqrtf(var + 1e-5f);
    }
    __syncthreads();
    float mu = s_mu, inv = s_inv;

    const float4 w0 = reinterpret_cast<const float4*>(lw)[tid];
    const float4 w1 = reinterpret_cast<const float4*>(lw)[tid + 256];
    const float4 b0 = reinterpret_cast<const float4*>(lb)[tid];
    const float4 b1 = reinterpret_cast<const float4*>(lb)[tid + 256];

    float4 o0, o1;
    o0.x = (v0.x - mu) * inv * w0.x + b0.x;
    o0.y = (v0.y - mu) * inv * w0.y + b0.y;
    o0.z = (v0.z - mu) * inv * w0.z + b0.z;
    o0.w = (v0.w - mu) * inv * w0.w + b0.w;
    o1.x = (v1.x - mu) * inv * w1.x + b1.x;
    o1.y = (v1.y - mu) * inv * w1.y + b1.y;
    o1.z = (v1.z - mu) * inv * w1.z + b1.z;
    o1.w = (v1.w - mu) * inv * w1.w + b1.w;
    orow[tid]       = o0;
    orow[tid + 256] = o1;
}

// ---------------- host orchestration ---------------------------------------
extern "C" void kernel_launch(void* const* d_in, const int* in_sizes, int n_in,
                              void* d_out, int out_size) {
    (void)in_sizes; (void)n_in; (void)out_size;
    const float* x      = (const float*)d_in[0];
    const float* Wq     = (const float*)d_in[1];
    const float* Wk     = (const float*)d_in[2];
    const float* Wv     = (const float*)d_in[3];
    const float* Wo     = (const float*)d_in[4];
    const float* conv_w = (const float*)d_in[5];
    const float* conv_b = (const float*)d_in[6];
    const float* gate_w = (const float*)d_in[7];
    const float* gate_b = (const float*)d_in[8];
    const float* ln_w   = (const float*)d_in[9];
    const float* ln_b   = (const float*)d_in[10];
    const float* gamma  = (const float*)d_in[11];

    __half *p_q, *p_k, *p_v, *p_gate;
    float  *p_y;
    __half *p_Wqt, *p_Wkt, *p_Wvt, *p_Wot, *p_Wgt;
    cudaGetSymbolAddress((void**)&p_q, g_q);
    cudaGetSymbolAddress((void**)&p_k, g_k);
    cudaGetSymbolAddress((void**)&p_v, g_v);
    cudaGetSymbolAddress((void**)&p_gate, g_gate);
    cudaGetSymbolAddress((void**)&p_y, g_y);
    cudaGetSymbolAddress((void**)&p_Wqt, g_Wqt);
    cudaGetSymbolAddress((void**)&p_Wkt, g_Wkt);
    cudaGetSymbolAddress((void**)&p_Wvt, g_Wvt);
    cudaGetSymbolAddress((void**)&p_Wot, g_Wot);
    cudaGetSymbolAddress((void**)&p_Wgt, g_Wgt);

    // allow 66KB dynamic smem on the GEMM kernels (idempotent)
    cudaFuncSetAttribute(gemm_qkvg_kernel, cudaFuncAttributeMaxDynamicSharedMemorySize, GEMM_SMEM);
    cudaFuncSetAttribute(gemm_out_kernel,  cudaFuncAttributeMaxDynamicSharedMemorySize, GEMM_SMEM);

    // 0) convert the 5 weight matrices to fp16 in one launch
    const int wBlocks = (Cc * Cc) / 2048;  // 2048 blocks per weight
    cvt5_f16_kernel<<<5 * wBlocks, 256>>>(Wq, p_Wqt, Wk, p_Wkt, Wv, p_Wvt,
                                          Wo, p_Wot, gate_w, p_Wgt);

    // 1) depthwise conv + SiLU (T-blocked); also emits fp16 x (g_xt)
    conv_silu_kernel<<<(Mrows / 4) * (Cc / 4) / 256, 256>>>(x, conv_w, conv_b);

    // 2) all four projections in ONE launch (q, k, v, gate) — fp16 outputs
    dim3 qgrid(64, Mrows / 128);   // 64 col-tiles (4 segs x 16), 128 row-tiles
    gemm_qkvg_kernel<<<qgrid, 256, GEMM_SMEM>>>(gate_b);

    // 3) decayed scan (chunked, exact); fp16 inputs, fp32 recurrence
    scan_pass1<<<Bb * Hh * NCHUNK / 4, 128>>>(p_k, p_v, gamma);
    scan_pass2<<<16, 128>>>(gamma);
    scan_pass3<<<Bb * Hh * NCHUNK / 4, 128>>>(p_k, p_v, p_q, p_gate, gamma);

    // 4) output projection (fp32 y) + LayerNorm
    dim3 ogrid(Cc / 128, Mrows / 128);   // (16, 128)
    gemm_out_kernel<<<ogrid, 256, GEMM_SMEM>>>();
    ln_kernel<<<Mrows, 256>>>(p_y, ln_w, ln_b, (float*)d_out);
}